// round 7
// baseline (speedup 1.0000x reference)
#include <cuda_runtime.h>
#include <math.h>

#define NROWS 12288
#define KDIM  512
#define FDIM  128
#define NB    8192
#define TMIN  (-12.0f)
#define TRANGE 24.0f
#define BCHUNK 64
#define NBCHUNK (NB / BCHUNK)   // 128

typedef unsigned long long ull;

// ---------------- scratch ------------------------------------------------------
__device__ float g_W[FDIM * KDIM];
__device__ float g_Z[NROWS * FDIM];
__device__ float g_s[NROWS];
__device__ int   g_hist[NB];
__device__ int   g_cum[NB];
__device__ float g_ESB[NB];                     // suffix Σ e over buckets > q
__device__ float g_BE[NB];                      // per-bucket Σ e
__device__ __align__(16) float g_BZ[NB * FDIM];  // per-bucket Σ z  -> in-place incl. prefix
__device__ __align__(16) float g_BEZ[NB * FDIM]; // per-bucket Σ e*z -> in-place incl. prefix
__device__ float g_cA[NBCHUNK * FDIM];
__device__ float g_cB[NBCHUNK * FDIM];
__device__ float g_cApre[NBCHUNK * FDIM];
__device__ float g_cBpre[NBCHUNK * FDIM];
__device__ float g_totB[FDIM];                  // Σ_all e*z per feature

__device__ __forceinline__ int bucket_of(float tv) {
    int q = (int)floorf((tv - TMIN) * (NB / TRANGE));
    return min(max(q, 0), NB - 1);
}
__device__ __forceinline__ void ffma2(ull& d, ull a, ull b, ull c) {
    asm("fma.rn.f32x2 %0, %1, %2, %3;" : "=l"(d) : "l"(a), "l"(b), "l"(c));
}
__device__ __forceinline__ ull dup2(float x) {
    ull d; asm("mov.b64 %0, {%1, %1};" : "=l"(d) : "f"(x)); return d;
}
__device__ __forceinline__ void unpack2(ull v, float& lo, float& hi) {
    asm("mov.b64 {%0, %1}, %2;" : "=f"(lo), "=f"(hi) : "l"(v));
}

// ---------------- K1: w = g * v / ||v|| ---------------------------------------
__global__ void k_prep(const float* __restrict__ v, const float* __restrict__ g) {
    int f = blockIdx.x;
    int tid = threadIdx.x;
    float ss = 0.f;
    for (int k = tid; k < KDIM; k += 128) { float x = v[f * KDIM + k]; ss += x * x; }
    #pragma unroll
    for (int o = 16; o; o >>= 1) ss += __shfl_xor_sync(0xffffffffu, ss, o);
    __shared__ float sm[4];
    if ((tid & 31) == 0) sm[tid >> 5] = ss;
    __syncthreads();
    float tot = sm[0] + sm[1] + sm[2] + sm[3];
    float c = g[f] / sqrtf(tot);
    for (int k = tid; k < KDIM; k += 128) g_W[f * KDIM + k] = c * v[f * KDIM + k];
}

// ---------------- K2: zero accumulators ---------------------------------------
__global__ __launch_bounds__(1024) void k_zero() {
    int idx = blockIdx.x * 1024 + threadIdx.x;   // 256 blocks -> 262144 threads
    float4 zz = make_float4(0.f, 0.f, 0.f, 0.f);
    ((float4*)g_BZ)[idx] = zz;
    ((float4*)g_BEZ)[idx] = zz;
    if (idx < NB) { g_hist[idx] = 0; g_BE[idx] = 0.f; }
}

// ---------------- K3: GEMM + fused s,t + bucket accumulation ------------------
// BM=32, BN=128, BK=32, 128 threads; 4 rows (f32x2-paired) x 8 cols / thread
__global__ __launch_bounds__(128) void k_gemm(const float* __restrict__ x,
                                              const float* __restrict__ bias,
                                              const float* __restrict__ aw) {
    __shared__ float As[32][34];     // [k][row]
    __shared__ ull   Bs[32][129];    // [k][col], value duplicated (b,b)
    int tid = threadIdx.x;
    int lane = tid & 31, w = tid >> 5;
    int row0 = blockIdx.x * 32;
    int mr = w * 8 + (lane >> 4) * 4;
    int cl = lane & 15;

    ull acc[2][8];
    #pragma unroll
    for (int m = 0; m < 2; m++)
        #pragma unroll
        for (int j = 0; j < 8; j++) acc[m][j] = 0ull;

    int ar = tid >> 2, akq = (tid & 3) * 4;
    int bf = tid >> 3, bkq = (tid & 7) * 4;

    for (int k0 = 0; k0 < KDIM; k0 += 32) {
        float4 d0 = *(const float4*)(x + (size_t)(row0 + ar) * KDIM + k0 + akq);
        float4 d1 = *(const float4*)(x + (size_t)(row0 + ar) * KDIM + k0 + akq + 16);
        float4 wv[8];
        #pragma unroll
        for (int u = 0; u < 8; u++)
            wv[u] = *(const float4*)(g_W + (size_t)(u * 16 + bf) * KDIM + k0 + bkq);
        __syncthreads();
        As[akq + 0][ar] = d0.x; As[akq + 1][ar] = d0.y;
        As[akq + 2][ar] = d0.z; As[akq + 3][ar] = d0.w;
        As[akq + 16][ar] = d1.x; As[akq + 17][ar] = d1.y;
        As[akq + 18][ar] = d1.z; As[akq + 19][ar] = d1.w;
        #pragma unroll
        for (int u = 0; u < 8; u++) {
            int f = u * 16 + bf;
            Bs[bkq + 0][f] = dup2(wv[u].x); Bs[bkq + 1][f] = dup2(wv[u].y);
            Bs[bkq + 2][f] = dup2(wv[u].z); Bs[bkq + 3][f] = dup2(wv[u].w);
        }
        __syncthreads();
        #pragma unroll 8
        for (int k = 0; k < 32; k++) {
            ull a01 = *(const ull*)&As[k][mr];
            ull a23 = *(const ull*)&As[k][mr + 2];
            #pragma unroll
            for (int j = 0; j < 8; j++) {
                ull bb = Bs[k][cl + 16 * j];
                ffma2(acc[0][j], a01, bb, acc[0][j]);
                ffma2(acc[1][j], a23, bb, acc[1][j]);
            }
        }
    }

    // epilogue: bias, store Z, s/t reduce, bucket atomics
    float zz[4][8];
    float ps[4] = {0.f, 0.f, 0.f, 0.f};
    float pt[4] = {0.f, 0.f, 0.f, 0.f};
    #pragma unroll
    for (int j = 0; j < 8; j++) {
        int c = cl + 16 * j;
        float bv = bias[c];
        float asrc = aw[c], adst = aw[FDIM + c];
        float z0, z1, z2, z3;
        unpack2(acc[0][j], z0, z1);
        unpack2(acc[1][j], z2, z3);
        z0 += bv; z1 += bv; z2 += bv; z3 += bv;
        zz[0][j] = z0; zz[1][j] = z1; zz[2][j] = z2; zz[3][j] = z3;
        g_Z[(size_t)(row0 + mr + 0) * FDIM + c] = z0;
        g_Z[(size_t)(row0 + mr + 1) * FDIM + c] = z1;
        g_Z[(size_t)(row0 + mr + 2) * FDIM + c] = z2;
        g_Z[(size_t)(row0 + mr + 3) * FDIM + c] = z3;
        ps[0] += asrc * z0; ps[1] += asrc * z1; ps[2] += asrc * z2; ps[3] += asrc * z3;
        pt[0] += adst * z0; pt[1] += adst * z1; pt[2] += adst * z2; pt[3] += adst * z3;
    }
    #pragma unroll
    for (int o = 1; o < 16; o <<= 1) {
        #pragma unroll
        for (int r = 0; r < 4; r++) {
            ps[r] += __shfl_xor_sync(0xffffffffu, ps[r], o);
            pt[r] += __shfl_xor_sync(0xffffffffu, pt[r], o);
        }
    }
    #pragma unroll
    for (int r = 0; r < 4; r++) {
        int q = bucket_of(pt[r]);
        float e = __expf(pt[r]);
        if (cl == 0) {
            g_s[row0 + mr + r] = ps[r];
            atomicAdd(&g_hist[q], 1);
            atomicAdd(&g_BE[q], e);
        }
        #pragma unroll
        for (int j = 0; j < 8; j++) {
            int c = cl + 16 * j;
            float z = zz[r][j];
            atomicAdd(&g_BZ[q * FDIM + c], z);
            atomicAdd(&g_BEZ[q * FDIM + c], e * z);
        }
    }
}

// ---------------- K4: hierarchical scan of hist + BE --------------------------
// cum[q] = inclusive count prefix; ESB[q] = totalE - inclusive E prefix
__global__ __launch_bounds__(1024) void k_scanhist() {
    __shared__ int   smI[32];
    __shared__ float smF[32];
    __shared__ int   smIex[32];
    __shared__ float smFex[32];
    __shared__ float smTot;
    int tid = threadIdx.x, lane = tid & 31, w = tid >> 5;
    int base = tid * 8;
    int ci[8]; float fe[8];
    int si = 0; float sf = 0.f;
    #pragma unroll
    for (int r = 0; r < 8; r++) {
        ci[r] = g_hist[base + r]; si += ci[r];
        fe[r] = g_BE[base + r];   sf += fe[r];
    }
    int li = si; float lf = sf;
    #pragma unroll
    for (int o = 1; o < 32; o <<= 1) {
        int vi = __shfl_up_sync(0xffffffffu, li, o);
        float vf = __shfl_up_sync(0xffffffffu, lf, o);
        if (lane >= o) { li += vi; lf += vf; }
    }
    if (lane == 31) { smI[w] = li; smF[w] = lf; }
    __syncthreads();
    if (w == 0) {
        int ti = smI[lane]; float tf = smF[lane];
        int ii = ti; float ff = tf;
        #pragma unroll
        for (int o = 1; o < 32; o <<= 1) {
            int vi = __shfl_up_sync(0xffffffffu, ii, o);
            float vf = __shfl_up_sync(0xffffffffu, ff, o);
            if (lane >= o) { ii += vi; ff += vf; }
        }
        smIex[lane] = ii - ti;
        smFex[lane] = ff - tf;
        if (lane == 31) smTot = ff;
    }
    __syncthreads();
    int runI = smIex[w] + (li - si);
    float runF = smFex[w] + (lf - sf);
    float totF = smTot;
    #pragma unroll
    for (int r = 0; r < 8; r++) {
        runI += ci[r];
        runF += fe[r];
        g_cum[base + r] = runI;
        g_ESB[base + r] = totF - runF;
    }
}

// ---------------- K5: chunk sums of BZ / BEZ ----------------------------------
__global__ __launch_bounds__(128) void kb_phase1() {
    int c = blockIdx.x, f = threadIdx.x;
    float a = 0.f, b = 0.f;
    #pragma unroll 4
    for (int k = 0; k < BCHUNK; k++) {
        int q = c * BCHUNK + k;
        a += g_BZ[q * FDIM + f];
        b += g_BEZ[q * FDIM + f];
    }
    g_cA[c * FDIM + f] = a;
    g_cB[c * FDIM + f] = b;
}

// ---------------- K6: inter-chunk exclusive scans (warp per feature) ----------
// NBCHUNK = 128 = 32 lanes * 4
__global__ __launch_bounds__(256) void kb_phase2() {
    int lane = threadIdx.x & 31;
    int f = blockIdx.x * 8 + (threadIdx.x >> 5);
    int cb = lane * 4;
    float a[4], b[4], lea[4], leb[4];
    float sa = 0.f, sb = 0.f;
    #pragma unroll
    for (int i = 0; i < 4; i++) {
        a[i] = g_cA[(cb + i) * FDIM + f];
        b[i] = g_cB[(cb + i) * FDIM + f];
    }
    #pragma unroll
    for (int i = 0; i < 4; i++) { lea[i] = sa; sa += a[i]; leb[i] = sb; sb += b[i]; }
    float ia = sa, ib = sb;
    #pragma unroll
    for (int o = 1; o < 32; o <<= 1) {
        float va = __shfl_up_sync(0xffffffffu, ia, o);
        float vb = __shfl_up_sync(0xffffffffu, ib, o);
        if (lane >= o) { ia += va; ib += vb; }
    }
    float exa = ia - sa, exb = ib - sb;
    #pragma unroll
    for (int i = 0; i < 4; i++) {
        g_cApre[(cb + i) * FDIM + f] = exa + lea[i];
        g_cBpre[(cb + i) * FDIM + f] = exb + leb[i];
    }
    if (lane == 31) g_totB[f] = ib;
}

// ---------------- K7: in-place inclusive prefix over buckets ------------------
__global__ __launch_bounds__(128) void kb_phase3() {
    int c = blockIdx.x, f = threadIdx.x;
    float runA = g_cApre[c * FDIM + f];
    float runB = g_cBpre[c * FDIM + f];
    #pragma unroll 4
    for (int k = 0; k < BCHUNK; k++) {
        int q = c * BCHUNK + k;
        runA += g_BZ[q * FDIM + f];
        runB += g_BEZ[q * FDIM + f];
        g_BZ[q * FDIM + f] = runA;    // inclusive prefix of Σz
        g_BEZ[q * FDIM + f] = runB;   // inclusive prefix of Σe*z
    }
}

// ---------------- K8: combine + residual + row softmax ------------------------
__global__ __launch_bounds__(128) void k_final(float* __restrict__ out) {
    int i = blockIdx.x, f = threadIdx.x;
    int lane = f & 31, warp = f >> 5;
    __shared__ float red[4];
    float si = g_s[i];
    int q = bucket_of(-si);
    int p = g_cum[q];
    float es = __expf(si);
    float denom = (float)p + es * g_ESB[q];
    float num = g_BZ[q * FDIM + f] + es * (g_totB[f] - g_BEZ[q * FDIM + f]);
    float z2 = num / denom + g_Z[(size_t)i * FDIM + f];
    float m = z2;
    #pragma unroll
    for (int o = 16; o; o >>= 1) m = fmaxf(m, __shfl_xor_sync(0xffffffffu, m, o));
    if (!lane) red[warp] = m;
    __syncthreads();
    m = fmaxf(fmaxf(red[0], red[1]), fmaxf(red[2], red[3]));
    float e = __expf(z2 - m);
    float ssum = e;
    #pragma unroll
    for (int o = 16; o; o >>= 1) ssum += __shfl_xor_sync(0xffffffffu, ssum, o);
    __syncthreads();
    if (!lane) red[warp] = ssum;
    __syncthreads();
    ssum = red[0] + red[1] + red[2] + red[3];
    out[(size_t)i * FDIM + f] = e / ssum;
}

// ---------------- launch ------------------------------------------------------
extern "C" void kernel_launch(void* const* d_in, const int* in_sizes, int n_in,
                              void* d_out, int out_size) {
    const float* x  = (const float*)d_in[0];
    const float* v  = (const float*)d_in[1];
    const float* g  = (const float*)d_in[2];
    const float* b  = (const float*)d_in[3];
    const float* aw = (const float*)d_in[4];
    float* out = (float*)d_out;

    k_prep<<<FDIM, 128>>>(v, g);
    k_zero<<<NB * FDIM / 4 / 1024, 1024>>>();
    k_gemm<<<NROWS / 32, 128>>>(x, b, aw);
    k_scanhist<<<1, 1024>>>();
    kb_phase1<<<NBCHUNK, 128>>>();
    kb_phase2<<<16, 256>>>();
    kb_phase3<<<NBCHUNK, 128>>>();
    k_final<<<NROWS, 128>>>(out);
}